// round 6
// baseline (speedup 1.0000x reference)
#include <cuda_runtime.h>

using ull = unsigned long long;

// ---------- packed f32x2 + MUFU helpers ----------
__device__ __forceinline__ ull pk2(float lo, float hi) {
    ull r; asm("mov.b64 %0, {%1, %2};" : "=l"(r) : "f"(lo), "f"(hi)); return r;
}
__device__ __forceinline__ void upk2(ull v, float& lo, float& hi) {
    asm("mov.b64 {%0, %1}, %2;" : "=f"(lo), "=f"(hi) : "l"(v));
}
__device__ __forceinline__ ull fma2(ull a, ull b, ull c) {
    ull d; asm("fma.rn.f32x2 %0, %1, %2, %3;" : "=l"(d) : "l"(a), "l"(b), "l"(c)); return d;
}
__device__ __forceinline__ ull add2(ull a, ull b) {
    ull d; asm("add.rn.f32x2 %0, %1, %2;" : "=l"(d) : "l"(a), "l"(b)); return d;
}
__device__ __forceinline__ float tanhf_hw(float x) {
    float y; asm("tanh.approx.f32 %0, %1;" : "=f"(y) : "f"(x)); return y;
}

#define HID 10
#define PF  4

// Layout: 10 lanes per batch element (lane = hidden unit, gates packed
// (i,f)/(g,o) in f32x2, 0.5 sigmoid-fold in weights). Each warp carries TWO
// independent 3-element streams (A: b0..b0+2, B: b0+3..b0+5) with separate
// h/c state but SHARED weight registers. The two streams are independent
// dependence chains, so ptxas statically interleaves them -> ILP-2 that
// hides the tanh/shfl/FMA chain latency that limited the 1-stream kernel.
__global__ void __launch_bounds__(32, 6)
lstm_dual_kernel(const float* __restrict__ x,
                 const float* __restrict__ w_ih,
                 const float* __restrict__ w_hh,
                 const float* __restrict__ b_ih,
                 const float* __restrict__ b_hh,
                 const float* __restrict__ fc_w,
                 const float* __restrict__ fc_b,
                 float* __restrict__ out,
                 int S, int B)
{
    const int lane = threadIdx.x & 31;
    const int wg   = blockIdx.x;

    int grp = lane / HID; if (grp > 2) grp = 2;            // lanes 30,31 -> grp 2
    int j   = lane - grp * HID; if (j >= HID) j = HID - 1; // clamp dup lanes
    const int gbase = grp * HID;

    int bA = wg * 6 + grp;
    int bB = wg * 6 + 3 + grp;
    const bool liveA = (bA < B) && (lane < 30) && (j == 0 || true); // per-lane live
    const bool liveB = (bB < B) && (lane < 30);
    if (bA >= B) bA = B - 1;
    if (bB >= B) bB = B - 1;

    // ---- shared per-lane packed weights (0.5 fold in i,f,o rows) ----
    ull whhA[HID], whhB[HID];
#pragma unroll
    for (int k = 0; k < HID; ++k) {
        whhA[k] = pk2(0.5f * w_hh[j * HID + k],
                      0.5f * w_hh[(HID + j) * HID + k]);
        whhB[k] = pk2(       w_hh[(2 * HID + j) * HID + k],
                      0.5f * w_hh[(3 * HID + j) * HID + k]);
    }
    const ull wx2A = pk2(0.5f * w_ih[j], 0.5f * w_ih[HID + j]);
    const ull wx2B = pk2(       w_ih[2 * HID + j], 0.5f * w_ih[3 * HID + j]);
    const ull b2A  = pk2(0.5f * (b_ih[j] + b_hh[j]),
                         0.5f * (b_ih[HID + j] + b_hh[HID + j]));
    const ull b2B  = pk2(        b_ih[2 * HID + j] + b_hh[2 * HID + j],
                         0.5f * (b_ih[3 * HID + j] + b_hh[3 * HID + j]));

    float fc[HID];
#pragma unroll
    for (int k = 0; k < HID; ++k) fc[k] = fc_w[k];
    const float fb = fc_b[0];

    // ---- per-stream state ----
    ull hdA[HID], hdB[HID];
#pragma unroll
    for (int k = 0; k < HID; ++k) { hdA[k] = 0ull; hdB[k] = 0ull; }
    float cA = 0.f, cB = 0.f;

    // LSTM cell for one stream; returns new h for this lane's unit.
    auto cell = [&](ull* hd, float& c, float xt) -> float {
        const ull xd = pk2(xt, xt);
        ull a0 = fma2(xd, wx2A, b2A);
        ull q0 = fma2(xd, wx2B, b2B);
        ull a1 = fma2(hd[1], whhA[1], 0ull);
        ull q1 = fma2(hd[1], whhB[1], 0ull);
#pragma unroll
        for (int k = 0; k < HID; k += 2) {
            a0 = fma2(hd[k], whhA[k], a0);
            q0 = fma2(hd[k], whhB[k], q0);
        }
#pragma unroll
        for (int k = 3; k < HID; k += 2) {
            a1 = fma2(hd[k], whhA[k], a1);
            q1 = fma2(hd[k], whhB[k], q1);
        }
        float si, sf, sg, so;
        upk2(add2(a0, a1), si, sf);
        upk2(add2(q0, q1), sg, so);
        const float ia = fmaf(0.5f, tanhf_hw(si), 0.5f);
        const float fa = fmaf(0.5f, tanhf_hw(sf), 0.5f);
        const float ga = tanhf_hw(sg);
        const float oa = fmaf(0.5f, tanhf_hw(so), 0.5f);
        const float cn = fmaf(ia, ga, fa * c);
        c = cn;
        return oa * tanhf_hw(cn);
    };

    // ---- x prefetch pipelines (PF deep per stream) ----
    float xbufA[PF], xbufB[PF];
#pragma unroll
    for (int i = 0; i < PF; ++i) {
        int ti = (i < S) ? i : (S - 1);
        xbufA[i] = __ldg(x + (size_t)ti * B + bA);
        xbufB[i] = __ldg(x + (size_t)ti * B + bB);
    }

    float* opA = out + bA;
    float* opB = out + bB;

    for (int t = 0; t < S; t += PF) {
#pragma unroll
        for (int u = 0; u < PF; ++u) {
            const float xtA = xbufA[u];
            const float xtB = xbufB[u];
            int tn = t + u + PF; tn = (tn < S) ? tn : (S - 1);
            xbufA[u] = __ldg(x + (size_t)tn * B + bA);
            xbufB[u] = __ldg(x + (size_t)tn * B + bB);

            // two independent cell updates (ptxas interleaves the chains)
            const float hnA = cell(hdA, cA, xtA);
            const float hnB = cell(hdB, cB, xtB);

            // broadcast h within group, fuse repack + fc head (per stream)
            float yA = fb, yB = fb;
#pragma unroll
            for (int m = 0; m < HID; ++m) {
                const float hAm = __shfl_sync(0xffffffffu, hnA, gbase + m, 32);
                const float hBm = __shfl_sync(0xffffffffu, hnB, gbase + m, 32);
                hdA[m] = pk2(hAm, hAm);
                hdB[m] = pk2(hBm, hBm);
                yA = fmaf(hAm, fc[m], yA);
                yB = fmaf(hBm, fc[m], yB);
            }

            if (liveA && j == 0 && lane < 30) *opA = yA;
            if (liveB && j == 0)              *opB = yB;
            opA += B;
            opB += B;
        }
    }
}

extern "C" void kernel_launch(void* const* d_in, const int* in_sizes, int n_in,
                              void* d_out, int out_size)
{
    const float* x    = (const float*)d_in[0];
    const float* w_ih = (const float*)d_in[1];
    const float* w_hh = (const float*)d_in[2];
    const float* b_ih = (const float*)d_in[3];
    const float* b_hh = (const float*)d_in[4];
    const float* fc_w = (const float*)d_in[5];
    const float* fc_b = (const float*)d_in[6];
    float* out = (float*)d_out;

    const int B = 4096;
    const int S = in_sizes[0] / B;   // 2048

    // 6 elements (two 3-elem streams) per one-warp block
    const int blocks = (B + 5) / 6;  // 683

    lstm_dual_kernel<<<blocks, 32>>>(x, w_ih, w_hh, b_ih, b_hh,
                                     fc_w, fc_b, out, S, B);
}

// round 7
// speedup vs baseline: 2.1825x; 2.1825x over previous
#include <cuda_runtime.h>

using ull = unsigned long long;

// ---------- packed f32x2 + MUFU helpers ----------
__device__ __forceinline__ ull pk2(float lo, float hi) {
    ull r; asm("mov.b64 %0, {%1, %2};" : "=l"(r) : "f"(lo), "f"(hi)); return r;
}
__device__ __forceinline__ void upk2(ull v, float& lo, float& hi) {
    asm("mov.b64 {%0, %1}, %2;" : "=f"(lo), "=f"(hi) : "l"(v));
}
__device__ __forceinline__ ull fma2(ull a, ull b, ull c) {
    ull d; asm("fma.rn.f32x2 %0, %1, %2, %3;" : "=l"(d) : "l"(a), "l"(b), "l"(c)); return d;
}
__device__ __forceinline__ float tanhf_hw(float x) {
    float y; asm("tanh.approx.f32 %0, %1;" : "=f"(y) : "f"(x)); return y;
}

#define HID 10
#define PF  4

// Layout: 10 lanes per batch element (lane j = hidden unit j), 3 elements per
// warp (lanes 30,31 duplicate lane 29's work; stores masked). Key changes vs
// the 409us kernel:
//  * h-exchange via SMEM ping-pong (1 STS + syncwarp + 2xLDS.128 + LDS.64)
//    instead of 10 SHFLs  -> removes the MIO/SHFL throughput term (~180cyc/SMSP-step).
//  * gate dots packed over k (h kept as 5 natural f32x2 pairs from LDS.128),
//    so the 10 duplicate-repack movs vanish.
//  * sigmoid = 0.5*(1+tanh(x/2)) with 0.5 folded into i/f/o weights: 1 MUFU/gate.
__global__ void __launch_bounds__(32, 16)
lstm_smem_kernel(const float* __restrict__ x,
                 const float* __restrict__ w_ih,
                 const float* __restrict__ w_hh,
                 const float* __restrict__ b_ih,
                 const float* __restrict__ b_hh,
                 const float* __restrict__ fc_w,
                 const float* __restrict__ fc_b,
                 float* __restrict__ out,
                 int S, int B)
{
    // ping-pong buffers, 3 groups, padded to 16 floats (64B) for LDS.128 align
    __shared__ float hsh[2][3][16];

    const int lane = threadIdx.x & 31;
    const int wg   = blockIdx.x;

    int grp = lane / HID; if (grp > 2) grp = 2;            // lanes 30,31 -> grp 2
    int j   = lane - grp * HID; if (j >= HID) j = HID - 1; // dup lanes -> j=9

    int b = wg * 3 + grp;
    const bool live = (b < B) && (lane < 30);
    if (b >= B) b = B - 1;                                 // safe-load clamp

    // ---- per-lane packed weights, packed over k-pairs ----
    // rows: 0=i(x0.5), 1=f(x0.5), 2=g(x1), 3=o(x0.5)
    ull w2[4][5];   // w2[r][p] = (sc*w_hh[row][2p], sc*w_hh[row][2p+1])
    ull wxb[4];     // (sc*w_ih[row], 0)
    ull bb2[4];     // (sc*(b_ih+b_hh)[row], 0)
#pragma unroll
    for (int r = 0; r < 4; ++r) {
        const float sc = (r == 2) ? 1.0f : 0.5f;
        const int row = r * HID + j;
#pragma unroll
        for (int p = 0; p < 5; ++p)
            w2[r][p] = pk2(sc * w_hh[row * HID + 2 * p],
                           sc * w_hh[row * HID + 2 * p + 1]);
        wxb[r] = pk2(sc * w_ih[row], 0.f);
        bb2[r] = pk2(sc * (b_ih[row] + b_hh[row]), 0.f);
    }

    ull fc2[5];
#pragma unroll
    for (int p = 0; p < 5; ++p) fc2[p] = pk2(fc_w[2 * p], fc_w[2 * p + 1]);
    const ull fb2 = pk2(fc_b[0], 0.f);

    // ---- state: h as 5 packed pairs (register-resident), c scalar ----
    ull hp[5];
#pragma unroll
    for (int p = 0; p < 5; ++p) hp[p] = 0ull;
    float c = 0.f;

    // ---- x prefetch pipeline ----
    float xbuf[PF];
#pragma unroll
    for (int i = 0; i < PF; ++i) {
        int ti = (i < S) ? i : (S - 1);
        xbuf[i] = __ldg(x + (size_t)ti * B + b);
    }

    float* op = out + b;
    int w = 0;  // ping-pong selector

    for (int t = 0; t < S; t += PF) {
#pragma unroll
        for (int u = 0; u < PF; ++u) {
            const float xt = xbuf[u];
            int tn = t + u + PF; tn = (tn < S) ? tn : (S - 1);
            xbuf[u] = __ldg(x + (size_t)tn * B + b);

            const ull xd = pk2(xt, xt);

            // 4 gate rows: init folds x & bias into lane0, then 5 k-pair fma2
            float s[4];
#pragma unroll
            for (int r = 0; r < 4; ++r) {
                ull acc = fma2(xd, wxb[r], bb2[r]);
#pragma unroll
                for (int p = 0; p < 5; ++p) acc = fma2(hp[p], w2[r][p], acc);
                float lo, hi; upk2(acc, lo, hi);
                s[r] = lo + hi;
            }

            const float ia = fmaf(0.5f, tanhf_hw(s[0]), 0.5f);
            const float fa = fmaf(0.5f, tanhf_hw(s[1]), 0.5f);
            const float ga = tanhf_hw(s[2]);
            const float oa = fmaf(0.5f, tanhf_hw(s[3]), 0.5f);

            const float cn = fmaf(ia, ga, fa * c);
            c = cn;
            const float hn = oa * tanhf_hw(cn);

            // ---- h exchange through smem (ping-pong) ----
            hsh[w][grp][j] = hn;
            __syncwarp();
            const float4 v0 = *(const float4*)&hsh[w][grp][0];
            const float4 v1 = *(const float4*)&hsh[w][grp][4];
            const float2 v2 = *(const float2*)&hsh[w][grp][8];
            hp[0] = pk2(v0.x, v0.y);
            hp[1] = pk2(v0.z, v0.w);
            hp[2] = pk2(v1.x, v1.y);
            hp[3] = pk2(v1.z, v1.w);
            hp[4] = pk2(v2.x, v2.y);
            w ^= 1;

            // ---- fc head on packed h ----
            ull y2 = fma2(hp[0], fc2[0], fb2);
#pragma unroll
            for (int p = 1; p < 5; ++p) y2 = fma2(hp[p], fc2[p], y2);
            float ylo, yhi; upk2(y2, ylo, yhi);

            if (live && j == 0) *op = ylo + yhi;
            op += B;
        }
    }
}

extern "C" void kernel_launch(void* const* d_in, const int* in_sizes, int n_in,
                              void* d_out, int out_size)
{
    const float* x    = (const float*)d_in[0];
    const float* w_ih = (const float*)d_in[1];
    const float* w_hh = (const float*)d_in[2];
    const float* b_ih = (const float*)d_in[3];
    const float* b_hh = (const float*)d_in[4];
    const float* fc_w = (const float*)d_in[5];
    const float* fc_b = (const float*)d_in[6];
    float* out = (float*)d_out;

    const int B = 4096;
    const int S = in_sizes[0] / B;   // 2048

    const int blocks = (B + 2) / 3;  // 1366 one-warp blocks, ~9.2 warps/SM

    lstm_smem_kernel<<<blocks, 32>>>(x, w_ih, w_hh, b_ih, b_hh,
                                     fc_w, fc_b, out, S, B);
}